// round 1
// baseline (speedup 1.0000x reference)
#include <cuda_runtime.h>
#include <math.h>

// 32x32 grid: packed = src_idx*8 + rot, or -1 if the cell is never written (masked).
__device__ int d_packed[1024];

// H=32, center=15.5. Octant positions (angle in [0, pi/4]): rows i=0..15,
// cols j=31-i..31, enumerated row-major -> idx = i*(i+1)/2 + (j-(31-i)).
// L = 136 positions, 8 rotations each = 1088 (idx,k) pairs.
// Reference writes src/rot sequentially with idx ascending (outer), k ascending
// (inner), last write wins => final value at a cell = max over writes of
// (idx*8+k). Reproduce via atomicMax on a -1-initialized table.
__global__ void build_tables_kernel() {
    const int tid = threadIdx.x;           // 1024 threads, single block
    d_packed[tid] = -1;
    __syncthreads();

    for (int pair = tid; pair < 136 * 8; pair += 1024) {
        int idx = pair >> 3;
        int k   = pair & 7;
        // decode idx -> (i, j): find row i with tri(i) <= idx < tri(i+1)
        int i = 0;
        while ((i + 1) * (i + 2) / 2 <= idx) i++;
        int j = (31 - i) + (idx - i * (i + 1) / 2);

        double y = 15.5 - (double)i;
        double x = (double)j - 15.5;
        double theta = (double)k * 3.141592653589793 / 4.0;
        double ct = cos(theta), st = sin(theta);
        double xn = ct * x - st * y;
        double yn = st * x + ct * y;
        // Python round() is half-to-even == rint; values never land on .5
        int ir = (int)rint(15.5 - yn);
        int jr = (int)rint(15.5 + xn);
        ir = max(0, min(31, ir));
        jr = max(0, min(31, jr));
        atomicMax(&d_packed[ir * 32 + jr], pair);
    }
}

// Fused gather + broadcast-add.
// Token layout: t=0 is CLS (cls_pos tiled x8), t=1+cell for cell in [0,1024).
// Each thread owns one float4 of the (1025 x 1024) embedding row and streams
// all 128 batches: out[b*S+p] = x[b*S+p] + f.
__global__ void __launch_bounds__(256) add_posembed_kernel(
    const float4* __restrict__ x,
    const float4* __restrict__ P,     // (136, 8, 128) f32 = 136*256 float4
    const float4* __restrict__ cls,   // 128 f32 = 32 float4
    float4* __restrict__ out)
{
    const int p = blockIdx.x * blockDim.x + threadIdx.x;  // 0 .. 262399
    const int NTOK4 = 1025 * 256;                         // float4 per batch
    if (p >= NTOK4) return;

    const int t  = p >> 8;    // token index 0..1024
    const int c4 = p & 255;   // float4 index within 1024 channels

    float4 f;
    if (t == 0) {
        f = cls[c4 & 31];                         // tile cls across 8 groups
    } else {
        int packed = d_packed[t - 1];
        if (packed < 0) {
            f = make_float4(0.f, 0.f, 0.f, 0.f);
        } else {
            int idx   = packed >> 3;
            int rot   = packed & 7;
            int k     = c4 >> 5;                  // which 128-channel group
            int group = (k - rot) & 7;
            f = P[idx * 256 + group * 32 + (c4 & 31)];
        }
    }

    size_t off = (size_t)p;
    const size_t stride = (size_t)NTOK4;
#pragma unroll 4
    for (int b = 0; b < 128; b++) {
        float4 v = x[off];
        v.x += f.x; v.y += f.y; v.z += f.z; v.w += f.w;
        out[off] = v;
        off += stride;
    }
}

extern "C" void kernel_launch(void* const* d_in, const int* in_sizes, int n_in,
                              void* d_out, int out_size) {
    const float4* x   = (const float4*)d_in[0];  // (128, 1025, 1024) f32
    const float4* P   = (const float4*)d_in[1];  // (1, 136, 1024) f32
    const float4* cls = (const float4*)d_in[2];  // (1, 1, 128) f32
    float4* out = (float4*)d_out;

    build_tables_kernel<<<1, 1024>>>();

    const int NTOK4 = 1025 * 256;                // 262400 float4 positions
    add_posembed_kernel<<<(NTOK4 + 255) / 256, 256>>>(x, P, cls, out);
}

// round 2
// speedup vs baseline: 1.1874x; 1.1874x over previous
#include <cuda_runtime.h>

// ---------------------------------------------------------------------------
// Compile-time rotation table.
// 32x32 grid, cell value = src_idx*8 + rot, or -1 if masked.
//
// Reference enumeration: positions (i,j) with atan2(15.5-i, j-15.5) in
// [0, pi/4+1e-6]. On half-integer coordinates this is exactly
// i<=15 && j>=31-i (the epsilon is dead: smallest ratio y/x above 1 is
// 1+1/15.5). Row-major enumeration gives idx; for each k=0..7 the rotated
// cell is overwritten sequentially => last-write-wins, same as reference.
//
// Trig: theta = k*pi/4 -> cos/sin in {±1, ±sqrt2/2, ~0}. libm doubles differ
// from these ideals by <=1 ulp (~1e-16); every rounded coordinate sits
// >=0.02 from a .5 boundary, so the table is identical (verified: R1 kernel
// using device cos/sin passed with rel_err == 0.0).
// ---------------------------------------------------------------------------
struct Table { int v[1024]; };

constexpr int iround(double v) {
    // equivalent to rint here: no value lands within 0.02 of a .5 boundary
    return v >= 0.0 ? (int)(v + 0.5) : -(int)(0.5 - v);
}
constexpr int iclamp31(int v) { return v < 0 ? 0 : (v > 31 ? 31 : v); }

constexpr Table make_table() {
    Table t{};
    for (int c = 0; c < 1024; c++) t.v[c] = -1;
    const double C0 = 0.7071067811865476;  // sqrt(2)/2, double-rounded
    const double ct[8] = {1.0, C0, 0.0, -C0, -1.0, -C0,  0.0,  C0};
    const double st[8] = {0.0, C0, 1.0,  C0,  0.0, -C0, -1.0, -C0};
    int idx = 0;
    for (int i = 0; i < 16; i++) {
        for (int j = 31 - i; j < 32; j++) {
            double y = 15.5 - (double)i;
            double x = (double)j - 15.5;
            for (int k = 0; k < 8; k++) {
                double xn = ct[k] * x - st[k] * y;
                double yn = st[k] * x + ct[k] * y;
                int ir = iclamp31(iround(15.5 - yn));
                int jr = iclamp31(iround(15.5 + xn));
                t.v[ir * 32 + jr] = idx * 8 + k;   // last write wins
            }
            idx++;
        }
    }
    return t;
}

__constant__ constexpr Table TBL = make_table();

// ---------------------------------------------------------------------------
// Fused gather + broadcast-add. One block == one token (256 float4 = 1024 ch).
// Each thread owns one float4 of the (1025 x 1024) embedding row, computes its
// embedding value f once, then streams all 128 batches:
//   out[b*S+p] = x[b*S+p] + f
// x/out have zero reuse -> evict-first streaming hints keep L2 clean.
// ---------------------------------------------------------------------------
__global__ void __launch_bounds__(256) add_posembed_kernel(
    const float4* __restrict__ x,
    const float4* __restrict__ P,     // (136, 8, 128) f32 = 136*256 float4
    const float4* __restrict__ cls,   // 128 f32 = 32 float4
    float4* __restrict__ out)
{
    const int p  = blockIdx.x * 256 + threadIdx.x;  // 0 .. 262399 (exact grid)
    const int t  = p >> 8;    // token index 0..1024 (uniform per block)
    const int c4 = p & 255;   // float4 index within 1024 channels

    float4 f;
    if (t == 0) {
        f = cls[c4 & 31];                         // tile cls across 8 groups
    } else {
        const int packed = TBL.v[t - 1];
        if (packed < 0) {
            f = make_float4(0.f, 0.f, 0.f, 0.f);
        } else {
            const int group = ((c4 >> 5) - (packed & 7)) & 7;
            f = P[(packed >> 3) * 256 + group * 32 + (c4 & 31)];
        }
    }

    size_t off = (size_t)p;
    const size_t stride = (size_t)(1025 * 256);
#pragma unroll 8
    for (int b = 0; b < 128; b++) {
        float4 v = __ldcs(x + off);
        v.x += f.x; v.y += f.y; v.z += f.z; v.w += f.w;
        __stcs(out + off, v);
        off += stride;
    }
}

extern "C" void kernel_launch(void* const* d_in, const int* in_sizes, int n_in,
                              void* d_out, int out_size) {
    const float4* x   = (const float4*)d_in[0];  // (128, 1025, 1024) f32
    const float4* P   = (const float4*)d_in[1];  // (1, 136, 1024) f32
    const float4* cls = (const float4*)d_in[2];  // (1, 1, 128) f32
    float4* out = (float4*)d_out;

    add_posembed_kernel<<<1025, 256>>>(x, P, cls, out);
}